// round 9
// baseline (speedup 1.0000x reference)
#include <cuda_runtime.h>
#include <cuda_bf16.h>
#include <math.h>
#include <stdint.h>

#define Bb 4
#define Tt 1024
#define Ee 512
#define Ss 1536
#define Hh 1024
#define NHh 16
#define HDd 64

// ---- scratch ----
__device__ float    g_qp[(size_t)Bb*Tt*Hh];
__device__ float    g_kp[(size_t)Bb*Tt*Hh];
__device__ float    g_vp[(size_t)Bb*Tt*Hh];
__device__ float    g_attn[(size_t)Bb*Tt*Hh];
__device__ unsigned g_xh[(size_t)Bb*Tt*Hh/2], g_xl[(size_t)Bb*Tt*Hh/2];
__device__ unsigned g_wqh[Hh*Hh/2], g_wql[Hh*Hh/2];
__device__ unsigned g_wkh[Hh*Hh/2], g_wkl[Hh*Hh/2];
__device__ unsigned g_wvh[Hh*Hh/2], g_wvl[Hh*Hh/2];
__device__ unsigned g_woh[Hh*Hh/2], g_wol[Hh*Hh/2];
__device__ unsigned g_nh[(size_t)Bb*Tt*Hh/2], g_nl[(size_t)Bb*Tt*Hh/2];
__device__ unsigned g_qh[(size_t)Bb*NHh*Tt*32], g_ql[(size_t)Bb*NHh*Tt*32];   // [bh][q][d2]
__device__ unsigned g_kh[(size_t)Bb*NHh*32*Ss], g_kl[(size_t)Bb*NHh*32*Ss];   // [bh][d2][s]
__device__ unsigned g_vh[(size_t)Bb*NHh*768*64], g_vl[(size_t)Bb*NHh*768*64]; // [bh][s2][d]

// ======================= helpers ============================================
__device__ __forceinline__ uint32_t smem_to_u32(const void* p) {
    uint32_t a;
    asm("{ .reg .u64 tmp; cvta.to.shared.u64 tmp, %1; cvt.u32.u64 %0, tmp; }"
        : "=r"(a) : "l"(p));
    return a;
}

__device__ __forceinline__ void mma_bf16(float c[4],
    unsigned a0, unsigned a1, unsigned a2, unsigned a3, unsigned b0, unsigned b1)
{
    asm volatile(
        "mma.sync.aligned.m16n8k16.row.col.f32.bf16.bf16.f32 "
        "{%0,%1,%2,%3}, {%4,%5,%6,%7}, {%8,%9}, {%0,%1,%2,%3};\n"
        : "+f"(c[0]), "+f"(c[1]), "+f"(c[2]), "+f"(c[3])
        : "r"(a0), "r"(a1), "r"(a2), "r"(a3), "r"(b0), "r"(b1));
}

#define LDSM_X4(r0, r1, r2, r3, a) \
    asm volatile("ldmatrix.sync.aligned.m8n8.x4.shared.b16 {%0,%1,%2,%3}, [%4];" \
                 : "=r"(r0), "=r"(r1), "=r"(r2), "=r"(r3) : "r"(a))

__device__ __forceinline__ void split2(float x, float y, unsigned &hi, unsigned &lo)
{
    __nv_bfloat16 hx = __float2bfloat16_rn(x);
    __nv_bfloat16 hy = __float2bfloat16_rn(y);
    __nv_bfloat16 lx = __float2bfloat16_rn(x - __bfloat162float(hx));
    __nv_bfloat16 ly = __float2bfloat16_rn(y - __bfloat162float(hy));
    hi = ((unsigned)__bfloat16_as_ushort(hy) << 16) | (unsigned)__bfloat16_as_ushort(hx);
    lo = ((unsigned)__bfloat16_as_ushort(ly) << 16) | (unsigned)__bfloat16_as_ushort(lx);
}

// ======================= fused split: all 5 tensors in one launch ===========
#define XP (Bb*Tt*Hh/2)
#define WP (Hh*Hh/2)
__global__ void splitk_all(const float* __restrict__ x,
                           const float* __restrict__ wq, const float* __restrict__ wk,
                           const float* __restrict__ wv, const float* __restrict__ wo,
                           unsigned* __restrict__ xh, unsigned* __restrict__ xl,
                           unsigned* __restrict__ wqh, unsigned* __restrict__ wql,
                           unsigned* __restrict__ wkh, unsigned* __restrict__ wkl,
                           unsigned* __restrict__ wvh, unsigned* __restrict__ wvl,
                           unsigned* __restrict__ woh, unsigned* __restrict__ wol)
{
    int i = blockIdx.x * 256 + threadIdx.x;
    const float* in; unsigned *ho, *lo2; int off; float alpha = 1.0f;
    if (i < XP)                 { in = x;  ho = xh;  lo2 = xl;  off = i; }
    else if (i < XP + WP)       { in = wq; ho = wqh; lo2 = wql; off = i - XP; alpha = 0.125f; }
    else if (i < XP + 2 * WP)   { in = wk; ho = wkh; lo2 = wkl; off = i - XP - WP; }
    else if (i < XP + 3 * WP)   { in = wv; ho = wvh; lo2 = wvl; off = i - XP - 2 * WP; }
    else if (i < XP + 4 * WP)   { in = wo; ho = woh; lo2 = wol; off = i - XP - 3 * WP; }
    else return;
    float2 v = ((const float2*)in)[off];
    unsigned h, l;
    split2(v.x * alpha, v.y * alpha, h, l);
    ho[off] = h; lo2[off] = l;
}

// ======================= mma.sync GEMM: C = X @ W^T (split-bf16 x3) =========
// Block tile 128x128, chunk K=64, 8 warps of 64x32.  Reg-prefetch pipelined.
#define GM_STRIDE 36
#define GM_SMEM_BYTES (4 * 128 * GM_STRIDE * 4)

__global__ __launch_bounds__(256)
void gemm_mma(const unsigned* __restrict__ Xh, const unsigned* __restrict__ Xl,
              const unsigned* __restrict__ Wh0, const unsigned* __restrict__ Wl0,
              const unsigned* __restrict__ Wh1, const unsigned* __restrict__ Wl1,
              const unsigned* __restrict__ Wh2, const unsigned* __restrict__ Wl2,
              float* __restrict__ C0, float* __restrict__ C1, float* __restrict__ C2,
              int N, int K)
{
    const unsigned* Wh = (blockIdx.z == 0) ? Wh0 : (blockIdx.z == 1) ? Wh1 : Wh2;
    const unsigned* Wl = (blockIdx.z == 0) ? Wl0 : (blockIdx.z == 1) ? Wl1 : Wl2;
    float*          C  = (blockIdx.z == 0) ? C0  : (blockIdx.z == 1) ? C1  : C2;

    extern __shared__ unsigned gs[];
    unsigned* Ah = gs;
    unsigned* Al = Ah + 128 * GM_STRIDE;
    unsigned* Bh = Al + 128 * GM_STRIDE;
    unsigned* Bl = Bh + 128 * GM_STRIDE;

    int t = threadIdx.x, lane = t & 31, w = t >> 5;
    int m0 = blockIdx.y * 128, n0 = blockIdx.x * 128;
    int K2 = K / 2;
    int wm = w >> 2, wn = w & 3;

    uint32_t sAh = smem_to_u32(Ah), sAl = smem_to_u32(Al);
    uint32_t sBh = smem_to_u32(Bh), sBl = smem_to_u32(Bl);

    int arow = wm * 64 + (lane & 15);
    uint32_t aoff = ((lane >> 4) * 4) * 4;
    int brow_base = wn * 32 + (lane & 7) + ((lane >> 3) & 1) * 8;
    uint32_t boff = ((lane >> 4) * 4) * 4;

    // staging mapping: 4 rows per thread group
    int srow[4], sc4[4];
    #pragma unroll
    for (int i = 0; i < 4; i++) {
        int idx = t + i * 256;
        srow[i] = idx >> 3; sc4[i] = idx & 7;
    }

    float acc[4][4][4] = {};
    float4 pf[4][4];   // [i][Ah/Al/Bh/Bl]

    // prefetch chunk 0
    #pragma unroll
    for (int i = 0; i < 4; i++) {
        pf[i][0] = *(const float4*)&Xh[(size_t)(m0 + srow[i]) * K2 + sc4[i] * 4];
        pf[i][1] = *(const float4*)&Xl[(size_t)(m0 + srow[i]) * K2 + sc4[i] * 4];
        pf[i][2] = *(const float4*)&Wh[(size_t)(n0 + srow[i]) * K2 + sc4[i] * 4];
        pf[i][3] = *(const float4*)&Wl[(size_t)(n0 + srow[i]) * K2 + sc4[i] * 4];
    }

    int nch = K / 64;
    for (int ch = 0; ch < nch; ch++) {
        __syncthreads();
        #pragma unroll
        for (int i = 0; i < 4; i++) {
            *(float4*)&Ah[srow[i] * GM_STRIDE + sc4[i] * 4] = pf[i][0];
            *(float4*)&Al[srow[i] * GM_STRIDE + sc4[i] * 4] = pf[i][1];
            *(float4*)&Bh[srow[i] * GM_STRIDE + sc4[i] * 4] = pf[i][2];
            *(float4*)&Bl[srow[i] * GM_STRIDE + sc4[i] * 4] = pf[i][3];
        }
        __syncthreads();
        if (ch + 1 < nch) {
            int kc = (ch + 1) * 32;
            #pragma unroll
            for (int i = 0; i < 4; i++) {
                pf[i][0] = *(const float4*)&Xh[(size_t)(m0 + srow[i]) * K2 + kc + sc4[i] * 4];
                pf[i][1] = *(const float4*)&Xl[(size_t)(m0 + srow[i]) * K2 + kc + sc4[i] * 4];
                pf[i][2] = *(const float4*)&Wh[(size_t)(n0 + srow[i]) * K2 + kc + sc4[i] * 4];
                pf[i][3] = *(const float4*)&Wl[(size_t)(n0 + srow[i]) * K2 + kc + sc4[i] * 4];
            }
        }

        #pragma unroll
        for (int ks = 0; ks < 4; ks++) {
            uint32_t kb = (ks * 8) * 4;
            unsigned bhf[2][4], blf[2][4];
            #pragma unroll
            for (int p = 0; p < 2; p++) {
                uint32_t ba = (brow_base + p * 16) * GM_STRIDE * 4 + kb + boff;
                LDSM_X4(bhf[p][0], bhf[p][1], bhf[p][2], bhf[p][3], sBh + ba);
                LDSM_X4(blf[p][0], blf[p][1], blf[p][2], blf[p][3], sBl + ba);
            }
            #pragma unroll
            for (int mt = 0; mt < 4; mt++) {
                uint32_t aa = (arow + mt * 16) * GM_STRIDE * 4 + kb + aoff;
                unsigned ah[4], al[4];
                LDSM_X4(ah[0], ah[1], ah[2], ah[3], sAh + aa);
                LDSM_X4(al[0], al[1], al[2], al[3], sAl + aa);
                #pragma unroll
                for (int nt = 0; nt < 4; nt++) {
                    unsigned b0 = bhf[nt >> 1][nt & 1], b1 = bhf[nt >> 1][2 + (nt & 1)];
                    unsigned c0 = blf[nt >> 1][nt & 1], c1 = blf[nt >> 1][2 + (nt & 1)];
                    mma_bf16(acc[mt][nt], ah[0], ah[1], ah[2], ah[3], b0, b1);
                    mma_bf16(acc[mt][nt], ah[0], ah[1], ah[2], ah[3], c0, c1);
                    mma_bf16(acc[mt][nt], al[0], al[1], al[2], al[3], b0, b1);
                }
            }
        }
    }

    int g = lane >> 2, t4 = lane & 3;
    #pragma unroll
    for (int mt = 0; mt < 4; mt++) {
        int row = m0 + wm * 64 + mt * 16 + g;
        #pragma unroll
        for (int nt = 0; nt < 4; nt++) {
            int col = n0 + wn * 32 + nt * 8 + 2 * t4;
            *(float2*)&C[(size_t)row * N + col]       = make_float2(acc[mt][nt][0], acc[mt][nt][1]);
            *(float2*)&C[(size_t)(row + 8) * N + col] = make_float2(acc[mt][nt][2], acc[mt][nt][3]);
        }
    }
}

// ======================= PBC expand + RoPE + pre-split ======================
__global__ __launch_bounds__(256)
void rope_expand_t(const int* __restrict__ outcell)
{
    __shared__ float sk[32][68];
    __shared__ float sv[32][68];
    int s0 = blockIdx.x * 32, h = blockIdx.y, b = blockIdx.z;
    int t = threadIdx.x;
    size_t bh = (size_t)b * NHh + h;
    const float LOG1E4 = 9.210340371976184f;

    #pragma unroll
    for (int i = 0; i < 2; i++) {
        int idx = t + i * 256;
        int r = idx >> 4, c4 = idx & 15;
        int s = s0 + r;
        int src = (s < Tt) ? s : outcell[b * Ee + (s - Tt)];
        *(float4*)&sk[r][c4 * 4] =
            ((const float4*)(g_kp + ((size_t)b * Tt + src) * Hh + h * 64))[c4];
        *(float4*)&sv[r][c4 * 4] =
            ((const float4*)(g_vp + ((size_t)b * Tt + src) * Hh + h * 64))[c4];
    }
    __syncthreads();

    // K: pairs along d, [bh][d2][s]
    #pragma unroll
    for (int i = 0; i < 4; i++) {
        int idx = t + i * 256;
        int d2 = idx >> 5, sl = idx & 31;
        int sabs = s0 + sl;
        int d0 = 2 * d2, d1 = d0 + 1;
        float invf0 = expf(-((float)(2 * (d0 & 31)) / 64.0f) * LOG1E4);
        float invf1 = expf(-((float)(2 * (d1 & 31)) / 64.0f) * LOG1E4);
        float a0 = (float)sabs * invf0, a1 = (float)sabs * invf1;
        float c0 = cosf(a0), n0 = sinf(a0), c1 = cosf(a1), n1 = sinf(a1);
        float v0 = (d0 < 32) ? sk[sl][d0] * c0 - sk[sl][d0 + 32] * n0
                             : sk[sl][d0] * c0 + sk[sl][d0 - 32] * n0;
        float v1 = (d1 < 32) ? sk[sl][d1] * c1 - sk[sl][d1 + 32] * n1
                             : sk[sl][d1] * c1 + sk[sl][d1 - 32] * n1;
        unsigned hp, lp; split2(v0, v1, hp, lp);
        g_kh[(bh * 32 + d2) * (size_t)Ss + sabs] = hp;
        g_kl[(bh * 32 + d2) * (size_t)Ss + sabs] = lp;
    }

    // V: pairs along s, [bh][s2][d]
    #pragma unroll
    for (int i = 0; i < 4; i++) {
        int idx = t + i * 256;
        int s2 = idx >> 6, d = idx & 63;
        unsigned hp, lp; split2(sv[2 * s2][d], sv[2 * s2 + 1][d], hp, lp);
        g_vh[(bh * 768 + (s0 >> 1) + s2) * 64 + d] = hp;
        g_vl[(bh * 768 + (s0 >> 1) + s2) * 64 + d] = lp;
    }

    if (s0 >= Tt) return;

    __syncthreads();
    #pragma unroll
    for (int i = 0; i < 2; i++) {
        int idx = t + i * 256;
        int r = idx >> 4, c4 = idx & 15;
        *(float4*)&sk[r][c4 * 4] =
            ((const float4*)(g_qp + ((size_t)b * Tt + s0 + r) * Hh + h * 64))[c4];
    }
    __syncthreads();
    // Q: pairs along d, [bh][q][d2]
    #pragma unroll
    for (int i = 0; i < 4; i++) {
        int idx = t + i * 256;
        int q = idx >> 5, d2 = idx & 31;
        int sabs = s0 + q;
        int d0 = 2 * d2, d1 = d0 + 1;
        float invf0 = expf(-((float)(2 * (d0 & 31)) / 64.0f) * LOG1E4);
        float invf1 = expf(-((float)(2 * (d1 & 31)) / 64.0f) * LOG1E4);
        float a0 = (float)sabs * invf0, a1 = (float)sabs * invf1;
        float c0 = cosf(a0), n0 = sinf(a0), c1 = cosf(a1), n1 = sinf(a1);
        float v0 = (d0 < 32) ? sk[q][d0] * c0 - sk[q][d0 + 32] * n0
                             : sk[q][d0] * c0 + sk[q][d0 - 32] * n0;
        float v1 = (d1 < 32) ? sk[q][d1] * c1 - sk[q][d1 + 32] * n1
                             : sk[q][d1] * c1 + sk[q][d1 - 32] * n1;
        unsigned hp, lp; split2(v0, v1, hp, lp);
        g_qh[((bh * Tt) + sabs) * 32 + d2] = hp;
        g_ql[((bh * Tt) + sabs) * 32 + d2] = lp;
    }
}

// ======================= Tensor-core flash attention ========================
#define ATT_SMEM_U32 (2*128*36 + 4*32*72 + 2*8*16*36)

__global__ __launch_bounds__(256)
void attn4(const float* __restrict__ bias, const float* __restrict__ lw,
           const unsigned char* __restrict__ kpm, const unsigned char* __restrict__ em)
{
    extern __shared__ unsigned su[];
    unsigned* Qh = su;                  // [128][36]
    unsigned* Ql = Qh + 128 * 36;
    unsigned* Kh = Ql + 128 * 36;       // [32][72]
    unsigned* Kl = Kh + 32 * 72;
    unsigned* Vh = Kl + 32 * 72;        // [32][72]
    unsigned* Vl = Vh + 32 * 72;
    unsigned* Ph = Vl + 32 * 72;        // per-warp [16][36]
    unsigned* Pl = Ph + 8 * 16 * 36;

    int t = threadIdx.x;
    int lane = t & 31, w = t >> 5;
    int g = lane >> 2, t4 = lane & 3;
    int qt = blockIdx.x, h = blockIdx.y, b = blockIdx.z;
    size_t bh = (size_t)b * NHh + h;
    int q0 = qt * 128;

    // stage Q (pre-split, packed pairs along d)
    #pragma unroll
    for (int i = 0; i < 4; i++) {
        int idx = t + i * 256;
        int q = idx >> 3, d4 = idx & 7;
        *(float4*)&Qh[q * 36 + d4 * 4] = *(const float4*)&g_qh[((bh * Tt) + q0 + q) * 32 + d4 * 4];
        *(float4*)&Ql[q * 36 + d4 * 4] = *(const float4*)&g_ql[((bh * Tt) + q0 + q) * 32 + d4 * 4];
    }

    float m0 = -INFINITY, m1 = -INFINITY, l0 = 0.f, l1 = 0.f;
    float oacc[8][4] = {};

    const float* biasr = bias + ((bh * Tt) + q0 + w * 16 + g) * (size_t)Ss;
    const float* lwr   = lw + ((size_t)b * Tt + q0 + w * 16 + g) * (size_t)Ss;
    unsigned* Phw = Ph + w * 16 * 36;
    unsigned* Plw = Pl + w * 16 * 36;

    // staging mapping (2 rows/thread) + K/V register prefetch
    int sr[2], sc4v[2];
    #pragma unroll
    for (int i = 0; i < 2; i++) {
        int idx = t + i * 256;
        sr[i] = idx >> 4; sc4v[i] = idx & 15;
    }
    float4 pKh[2], pKl[2], pVh[2], pVl[2];
    #pragma unroll
    for (int i = 0; i < 2; i++) {
        pKh[i] = *(const float4*)&g_kh[(bh * 32 + sr[i]) * (size_t)Ss + sc4v[i] * 4];
        pKl[i] = *(const float4*)&g_kl[(bh * 32 + sr[i]) * (size_t)Ss + sc4v[i] * 4];
        pVh[i] = *(const float4*)&g_vh[(bh * 768 + sr[i]) * 64 + sc4v[i] * 4];
        pVl[i] = *(const float4*)&g_vl[(bh * 768 + sr[i]) * 64 + sc4v[i] * 4];
    }

    for (int kt = 0; kt < Ss / 64; kt++) {
        int k0 = kt * 64;
        __syncthreads();
        #pragma unroll
        for (int i = 0; i < 2; i++) {
            *(float4*)&Kh[sr[i] * 72 + sc4v[i] * 4] = pKh[i];
            *(float4*)&Kl[sr[i] * 72 + sc4v[i] * 4] = pKl[i];
            *(float4*)&Vh[sr[i] * 72 + sc4v[i] * 4] = pVh[i];
            *(float4*)&Vl[sr[i] * 72 + sc4v[i] * 4] = pVl[i];
        }
        __syncthreads();
        if (kt + 1 < Ss / 64) {
            int k1 = (kt + 1) * 64;
            #pragma unroll
            for (int i = 0; i < 2; i++) {
                pKh[i] = *(const float4*)&g_kh[(bh * 32 + sr[i]) * (size_t)Ss + k1 + sc4v[i] * 4];
                pKl[i] = *(const float4*)&g_kl[(bh * 32 + sr[i]) * (size_t)Ss + k1 + sc4v[i] * 4];
                pVh[i] = *(const float4*)&g_vh[(bh * 768 + (k1 >> 1) + sr[i]) * 64 + sc4v[i] * 4];
                pVl[i] = *(const float4*)&g_vl[(bh * 768 + (k1 >> 1) + sr[i]) * 64 + sc4v[i] * 4];
            }
        }

        // QK: 16q x 64k per warp
        float sc[8][4];
        #pragma unroll
        for (int ns = 0; ns < 8; ns++)
            #pragma unroll
            for (int j = 0; j < 4; j++) sc[ns][j] = 0.f;

        int qb = w * 16;
        #pragma unroll
        for (int dc = 0; dc < 4; dc++) {
            unsigned ah0 = Qh[(qb + g) * 36 + dc * 8 + t4];
            unsigned ah1 = Qh[(qb + g + 8) * 36 + dc * 8 + t4];
            unsigned ah2 = Qh[(qb + g) * 36 + dc * 8 + t4 + 4];
            unsigned ah3 = Qh[(qb + g + 8) * 36 + dc * 8 + t4 + 4];
            unsigned al0 = Ql[(qb + g) * 36 + dc * 8 + t4];
            unsigned al1 = Ql[(qb + g + 8) * 36 + dc * 8 + t4];
            unsigned al2 = Ql[(qb + g) * 36 + dc * 8 + t4 + 4];
            unsigned al3 = Ql[(qb + g + 8) * 36 + dc * 8 + t4 + 4];
            #pragma unroll
            for (int ns = 0; ns < 8; ns++) {
                unsigned bh0 = Kh[(dc * 8 + t4) * 72 + ns * 8 + g];
                unsigned bh1 = Kh[(dc * 8 + t4 + 4) * 72 + ns * 8 + g];
                unsigned bl0 = Kl[(dc * 8 + t4) * 72 + ns * 8 + g];
                unsigned bl1 = Kl[(dc * 8 + t4 + 4) * 72 + ns * 8 + g];
                mma_bf16(sc[ns], ah0, ah1, ah2, ah3, bh0, bh1);
                mma_bf16(sc[ns], ah0, ah1, ah2, ah3, bl0, bl1);
                mma_bf16(sc[ns], al0, al1, al2, al3, bh0, bh1);
            }
        }

        // bias + masks
        float lwv[8][4];
        float tm0 = -INFINITY, tm1 = -INFINITY;
        #pragma unroll
        for (int ns = 0; ns < 8; ns++) {
            int kb = k0 + ns * 8 + 2 * t4;
            float2 b0v = *(const float2*)(biasr + kb);
            float2 b1v = *(const float2*)(biasr + 8 * (size_t)Ss + kb);
            float2 l0v = *(const float2*)(lwr + kb);
            float2 l1v = *(const float2*)(lwr + 8 * (size_t)Ss + kb);
            unsigned char ma0, ma1;
            if (k0 < Tt) { ma0 = kpm[b * Tt + kb]; ma1 = kpm[b * Tt + kb + 1]; }
            else         { ma0 = em[b * Ee + kb - Tt]; ma1 = em[b * Ee + kb - Tt + 1]; }
            sc[ns][0] = (l0v.x <= 1e-5f || ma0) ? -INFINITY : sc[ns][0] + b0v.x;
            sc[ns][1] = (l0v.y <= 1e-5f || ma1) ? -INFINITY : sc[ns][1] + b0v.y;
            sc[ns][2] = (l1v.x <= 1e-5f || ma0) ? -INFINITY : sc[ns][2] + b1v.x;
            sc[ns][3] = (l1v.y <= 1e-5f || ma1) ? -INFINITY : sc[ns][3] + b1v.y;
            lwv[ns][0] = l0v.x; lwv[ns][1] = l0v.y;
            lwv[ns][2] = l1v.x; lwv[ns][3] = l1v.y;
            tm0 = fmaxf(tm0, fmaxf(sc[ns][0], sc[ns][1]));
            tm1 = fmaxf(tm1, fmaxf(sc[ns][2], sc[ns][3]));
        }
        tm0 = fmaxf(tm0, __shfl_xor_sync(0xffffffffu, tm0, 1));
        tm0 = fmaxf(tm0, __shfl_xor_sync(0xffffffffu, tm0, 2));
        tm1 = fmaxf(tm1, __shfl_xor_sync(0xffffffffu, tm1, 1));
        tm1 = fmaxf(tm1, __shfl_xor_sync(0xffffffffu, tm1, 2));

        float mn0 = fmaxf(m0, tm0);
        float mn1 = fmaxf(m1, tm1);
        float scl0 = (mn0 > -INFINITY) ? __expf(m0 - mn0) : 1.0f;
        float scl1 = (mn1 > -INFINITY) ? __expf(m1 - mn1) : 1.0f;
        float mc0 = (mn0 > -INFINITY) ? mn0 : 0.0f;
        float mc1 = (mn1 > -INFINITY) ? mn1 : 0.0f;

        float es0 = 0.f, es1 = 0.f;
        #pragma unroll
        for (int ns = 0; ns < 8; ns++) {
            float e0 = __expf(sc[ns][0] - mc0);
            float e1 = __expf(sc[ns][1] - mc0);
            float e2 = __expf(sc[ns][2] - mc1);
            float e3 = __expf(sc[ns][3] - mc1);
            es0 += e0 + e1; es1 += e2 + e3;
            unsigned hp, lp;
            split2(e0 * lwv[ns][0], e1 * lwv[ns][1], hp, lp);
            Phw[g * 36 + ns * 4 + t4] = hp;
            Plw[g * 36 + ns * 4 + t4] = lp;
            split2(e2 * lwv[ns][2], e3 * lwv[ns][3], hp, lp);
            Phw[(g + 8) * 36 + ns * 4 + t4] = hp;
            Plw[(g + 8) * 36 + ns * 4 + t4] = lp;
        }
        es0 += __shfl_xor_sync(0xffffffffu, es0, 1);
        es0 += __shfl_xor_sync(0xffffffffu, es0, 2);
        es1 += __shfl_xor_sync(0xffffffffu, es1, 1);
        es1 += __shfl_xor_sync(0xffffffffu, es1, 2);
        l0 = l0 * scl0 + es0; m0 = mn0;
        l1 = l1 * scl1 + es1; m1 = mn1;

        #pragma unroll
        for (int ns = 0; ns < 8; ns++) {
            oacc[ns][0] *= scl0; oacc[ns][1] *= scl0;
            oacc[ns][2] *= scl1; oacc[ns][3] *= scl1;
        }
        __syncwarp();

        // PV
        #pragma unroll
        for (int kc = 0; kc < 4; kc++) {
            unsigned ah0 = Phw[g * 36 + kc * 8 + t4];
            unsigned ah1 = Phw[(g + 8) * 36 + kc * 8 + t4];
            unsigned ah2 = Phw[g * 36 + kc * 8 + t4 + 4];
            unsigned ah3 = Phw[(g + 8) * 36 + kc * 8 + t4 + 4];
            unsigned al0 = Plw[g * 36 + kc * 8 + t4];
            unsigned al1 = Plw[(g + 8) * 36 + kc * 8 + t4];
            unsigned al2 = Plw[g * 36 + kc * 8 + t4 + 4];
            unsigned al3 = Plw[(g + 8) * 36 + kc * 8 + t4 + 4];
            #pragma unroll
            for (int ns = 0; ns < 8; ns++) {
                unsigned b0 = Vh[(kc * 8 + t4) * 72 + ns * 8 + g];
                unsigned b1 = Vh[(kc * 8 + t4 + 4) * 72 + ns * 8 + g];
                unsigned c0 = Vl[(kc * 8 + t4) * 72 + ns * 8 + g];
                unsigned c1 = Vl[(kc * 8 + t4 + 4) * 72 + ns * 8 + g];
                mma_bf16(oacc[ns], ah0, ah1, ah2, ah3, b0, b1);
                mma_bf16(oacc[ns], ah0, ah1, ah2, ah3, c0, c1);
                mma_bf16(oacc[ns], al0, al1, al2, al3, b0, b1);
            }
        }
    }

    float i0 = 1.0f / l0, i1 = 1.0f / l1;
    int r0 = q0 + w * 16 + g;
    #pragma unroll
    for (int ns = 0; ns < 8; ns++) {
        float2 o0 = make_float2(oacc[ns][0] * i0, oacc[ns][1] * i0);
        float2 o1 = make_float2(oacc[ns][2] * i1, oacc[ns][3] * i1);
        *(float2*)&g_attn[((size_t)b * Tt + r0) * Hh + h * 64 + ns * 8 + 2 * t4] = o0;
        *(float2*)&g_attn[((size_t)b * Tt + r0 + 8) * Hh + h * 64 + ns * 8 + 2 * t4] = o1;
    }
}

// ---- layernorm over H=1024, emits packed hi/lo for out-proj GEMM ----
__global__ void ln_kernel(const float* __restrict__ gamma, const float* __restrict__ beta)
{
    int row = blockIdx.x;
    int tid = threadIdx.x;
    float4 v = *(const float4*)&g_attn[(size_t)row * Hh + tid * 4];
    float s = v.x + v.y + v.z + v.w;
    float s2 = v.x * v.x + v.y * v.y + v.z * v.z + v.w * v.w;
    __shared__ float rs[256], rs2[256];
    rs[tid] = s; rs2[tid] = s2;
    __syncthreads();
    for (int st = 128; st > 0; st >>= 1) {
        if (tid < st) { rs[tid] += rs[tid + st]; rs2[tid] += rs2[tid + st]; }
        __syncthreads();
    }
    float mean = rs[0] * (1.0f / Hh);
    float var  = rs2[0] * (1.0f / Hh) - mean * mean;
    float r = rsqrtf(var + 1e-5f);
    float4 gm = *(const float4*)&gamma[tid * 4];
    float4 bt = *(const float4*)&beta[tid * 4];
    float n0 = (v.x - mean) * r * gm.x + bt.x;
    float n1 = (v.y - mean) * r * gm.y + bt.y;
    float n2 = (v.z - mean) * r * gm.z + bt.z;
    float n3 = (v.w - mean) * r * gm.w + bt.w;
    unsigned h0, l0v, h1, l1v;
    split2(n0, n1, h0, l0v);
    split2(n2, n3, h1, l1v);
    *(uint2*)&g_nh[(size_t)row * 512 + tid * 2] = make_uint2(h0, h1);
    *(uint2*)&g_nl[(size_t)row * 512 + tid * 2] = make_uint2(l0v, l1v);
}

extern "C" void kernel_launch(void* const* d_in, const int* in_sizes, int n_in,
                              void* d_out, int out_size)
{
    const float* x    = (const float*)d_in[0];
    const float* bias = (const float*)d_in[1];
    const float* lw   = (const float*)d_in[2];
    const unsigned char* kpm = (const unsigned char*)d_in[3];
    const int*   outcell = (const int*)d_in[4];
    const unsigned char* em  = (const unsigned char*)d_in[5];
    const float* wq   = (const float*)d_in[6];
    const float* wk   = (const float*)d_in[7];
    const float* wv   = (const float*)d_in[8];
    const float* wout = (const float*)d_in[9];
    const float* lng  = (const float*)d_in[10];
    const float* lnb  = (const float*)d_in[11];

    float *qp, *kp, *vp;
    unsigned *xh, *xl, *wqh, *wql, *wkh, *wkl, *wvh, *wvl, *woh, *wol, *nh, *nl;
    cudaGetSymbolAddress((void**)&qp,  g_qp);
    cudaGetSymbolAddress((void**)&kp,  g_kp);
    cudaGetSymbolAddress((void**)&vp,  g_vp);
    cudaGetSymbolAddress((void**)&xh,  g_xh);  cudaGetSymbolAddress((void**)&xl,  g_xl);
    cudaGetSymbolAddress((void**)&wqh, g_wqh); cudaGetSymbolAddress((void**)&wql, g_wql);
    cudaGetSymbolAddress((void**)&wkh, g_wkh); cudaGetSymbolAddress((void**)&wkl, g_wkl);
    cudaGetSymbolAddress((void**)&wvh, g_wvh); cudaGetSymbolAddress((void**)&wvl, g_wvl);
    cudaGetSymbolAddress((void**)&woh, g_woh); cudaGetSymbolAddress((void**)&wol, g_wol);
    cudaGetSymbolAddress((void**)&nh,  g_nh);  cudaGetSymbolAddress((void**)&nl,  g_nl);

    static int attr_set = 0;
    if (!attr_set) {
        cudaFuncSetAttribute(attn4, cudaFuncAttributeMaxDynamicSharedMemorySize,
                             ATT_SMEM_U32 * 4);
        cudaFuncSetAttribute(gemm_mma, cudaFuncAttributeMaxDynamicSharedMemorySize,
                             GM_SMEM_BYTES);
        attr_set = 1;
    }

    // fused pre-split of x + all 4 weights (wq scaled by 0.125)
    int tot = XP + 4 * WP;
    splitk_all<<<(tot + 255) / 256, 256>>>(x, wq, wk, wv, wout,
        xh, xl, wqh, wql, wkh, wkl, wvh, wvl, woh, wol);

    // QKV projection on tensor cores
    gemm_mma<<<dim3(Hh / 128, (Bb * Tt) / 128, 3), 256, GM_SMEM_BYTES>>>(
        xh, xl, wqh, wql, wkh, wkl, wvh, wvl, qp, kp, vp, Hh, Hh);

    rope_expand_t<<<dim3(Ss / 32, NHh, Bb), 256>>>(outcell);

    attn4<<<dim3(Tt / 128, NHh, Bb), 256, ATT_SMEM_U32 * 4>>>(bias, lw, kpm, em);

    ln_kernel<<<Bb * Tt, 256>>>(lng, lnb);

    // output projection on tensor cores
    gemm_mma<<<dim3(Hh / 128, (Bb * Tt) / 128, 1), 256, GM_SMEM_BYTES>>>(
        nh, nl, woh, wol, woh, wol, woh, wol,
        (float*)d_out, (float*)d_out, (float*)d_out, Hh, Hh);
}

// round 11
// speedup vs baseline: 1.2884x; 1.2884x over previous
#include <cuda_runtime.h>
#include <cuda_bf16.h>
#include <math.h>
#include <stdint.h>

#define Bb 4
#define Tt 1024
#define Ee 512
#define Ss 1536
#define Hh 1024
#define NHh 16
#define HDd 64

// ---- scratch ----
__device__ float    g_qp[(size_t)Bb*Tt*Hh];
__device__ float    g_kp[(size_t)Bb*Tt*Hh];
__device__ float    g_vp[(size_t)Bb*Tt*Hh];
__device__ float    g_attn[(size_t)Bb*Tt*Hh];
__device__ unsigned g_xh[(size_t)Bb*Tt*Hh/2], g_xl[(size_t)Bb*Tt*Hh/2];
__device__ unsigned g_wqh[Hh*Hh/2], g_wql[Hh*Hh/2];
__device__ unsigned g_wkh[Hh*Hh/2], g_wkl[Hh*Hh/2];
__device__ unsigned g_wvh[Hh*Hh/2], g_wvl[Hh*Hh/2];
__device__ unsigned g_woh[Hh*Hh/2], g_wol[Hh*Hh/2];
__device__ unsigned g_nh[(size_t)Bb*Tt*Hh/2], g_nl[(size_t)Bb*Tt*Hh/2];
__device__ unsigned g_qh[(size_t)Bb*NHh*Tt*32], g_ql[(size_t)Bb*NHh*Tt*32];   // [bh][q][d2]
__device__ unsigned g_kh[(size_t)Bb*NHh*32*Ss], g_kl[(size_t)Bb*NHh*32*Ss];   // [bh][d2][s]
__device__ unsigned g_vh[(size_t)Bb*NHh*768*64], g_vl[(size_t)Bb*NHh*768*64]; // [bh][s2][d]

// ======================= helpers ============================================
__device__ __forceinline__ uint32_t smem_to_u32(const void* p) {
    uint32_t a;
    asm("{ .reg .u64 tmp; cvta.to.shared.u64 tmp, %1; cvt.u32.u64 %0, tmp; }"
        : "=r"(a) : "l"(p));
    return a;
}

__device__ __forceinline__ void mma_bf16(float c[4],
    unsigned a0, unsigned a1, unsigned a2, unsigned a3, unsigned b0, unsigned b1)
{
    asm volatile(
        "mma.sync.aligned.m16n8k16.row.col.f32.bf16.bf16.f32 "
        "{%0,%1,%2,%3}, {%4,%5,%6,%7}, {%8,%9}, {%0,%1,%2,%3};\n"
        : "+f"(c[0]), "+f"(c[1]), "+f"(c[2]), "+f"(c[3])
        : "r"(a0), "r"(a1), "r"(a2), "r"(a3), "r"(b0), "r"(b1));
}

#define LDSM_X4(r0, r1, r2, r3, a) \
    asm volatile("ldmatrix.sync.aligned.m8n8.x4.shared.b16 {%0,%1,%2,%3}, [%4];" \
                 : "=r"(r0), "=r"(r1), "=r"(r2), "=r"(r3) : "r"(a))

#define CP16(dst, src) \
    asm volatile("cp.async.cg.shared.global [%0], [%1], 16;" :: "r"(dst), "l"(src))
#define CP_COMMIT() asm volatile("cp.async.commit_group;" ::: "memory")

__device__ __forceinline__ void split2(float x, float y, unsigned &hi, unsigned &lo)
{
    __nv_bfloat16 hx = __float2bfloat16_rn(x);
    __nv_bfloat16 hy = __float2bfloat16_rn(y);
    __nv_bfloat16 lx = __float2bfloat16_rn(x - __bfloat162float(hx));
    __nv_bfloat16 ly = __float2bfloat16_rn(y - __bfloat162float(hy));
    hi = ((unsigned)__bfloat16_as_ushort(hy) << 16) | (unsigned)__bfloat16_as_ushort(hx);
    lo = ((unsigned)__bfloat16_as_ushort(ly) << 16) | (unsigned)__bfloat16_as_ushort(lx);
}

// ======================= fused split: all 5 tensors in one launch ===========
#define XP (Bb*Tt*Hh/2)
#define WP (Hh*Hh/2)
__global__ void splitk_all(const float* __restrict__ x,
                           const float* __restrict__ wq, const float* __restrict__ wk,
                           const float* __restrict__ wv, const float* __restrict__ wo,
                           unsigned* __restrict__ xh, unsigned* __restrict__ xl,
                           unsigned* __restrict__ wqh, unsigned* __restrict__ wql,
                           unsigned* __restrict__ wkh, unsigned* __restrict__ wkl,
                           unsigned* __restrict__ wvh, unsigned* __restrict__ wvl,
                           unsigned* __restrict__ woh, unsigned* __restrict__ wol)
{
    int i = blockIdx.x * 256 + threadIdx.x;
    const float* in; unsigned *ho, *lo2; int off; float alpha = 1.0f;
    if (i < XP)                 { in = x;  ho = xh;  lo2 = xl;  off = i; }
    else if (i < XP + WP)       { in = wq; ho = wqh; lo2 = wql; off = i - XP; alpha = 0.125f; }
    else if (i < XP + 2 * WP)   { in = wk; ho = wkh; lo2 = wkl; off = i - XP - WP; }
    else if (i < XP + 3 * WP)   { in = wv; ho = wvh; lo2 = wvl; off = i - XP - 2 * WP; }
    else if (i < XP + 4 * WP)   { in = wo; ho = woh; lo2 = wol; off = i - XP - 3 * WP; }
    else return;
    float2 v = ((const float2*)in)[off];
    unsigned h, l;
    split2(v.x * alpha, v.y * alpha, h, l);
    ho[off] = h; lo2[off] = l;
}

// ======================= mma.sync GEMM (round-6 form, known good) ===========
#define GM_STRIDE 36
#define GM_SMEM_BYTES (4 * 128 * GM_STRIDE * 4)

__global__ __launch_bounds__(256)
void gemm_mma(const unsigned* __restrict__ Xh, const unsigned* __restrict__ Xl,
              const unsigned* __restrict__ Wh0, const unsigned* __restrict__ Wl0,
              const unsigned* __restrict__ Wh1, const unsigned* __restrict__ Wl1,
              const unsigned* __restrict__ Wh2, const unsigned* __restrict__ Wl2,
              float* __restrict__ C0, float* __restrict__ C1, float* __restrict__ C2,
              int N, int K)
{
    const unsigned* Wh = (blockIdx.z == 0) ? Wh0 : (blockIdx.z == 1) ? Wh1 : Wh2;
    const unsigned* Wl = (blockIdx.z == 0) ? Wl0 : (blockIdx.z == 1) ? Wl1 : Wl2;
    float*          C  = (blockIdx.z == 0) ? C0  : (blockIdx.z == 1) ? C1  : C2;

    extern __shared__ unsigned gs[];
    unsigned* Ah = gs;
    unsigned* Al = Ah + 128 * GM_STRIDE;
    unsigned* Bh = Al + 128 * GM_STRIDE;
    unsigned* Bl = Bh + 128 * GM_STRIDE;

    int t = threadIdx.x, lane = t & 31, w = t >> 5;
    int m0 = blockIdx.y * 128, n0 = blockIdx.x * 128;
    int K2 = K / 2;
    int wm = w >> 2, wn = w & 3;

    uint32_t sAh = smem_to_u32(Ah), sAl = smem_to_u32(Al);
    uint32_t sBh = smem_to_u32(Bh), sBl = smem_to_u32(Bl);

    int arow = wm * 64 + (lane & 15);
    uint32_t aoff = ((lane >> 4) * 4) * 4;
    int brow_base = wn * 32 + (lane & 7) + ((lane >> 3) & 1) * 8;
    uint32_t boff = ((lane >> 4) * 4) * 4;

    float acc[4][4][4] = {};

    int nch = K / 64;
    for (int ch = 0; ch < nch; ch++) {
        int kc = ch * 32;
        __syncthreads();
        #pragma unroll
        for (int i = 0; i < 4; i++) {
            int idx = t + i * 256;
            int r = idx >> 3, c4 = idx & 7;
            *(float4*)&Ah[r * GM_STRIDE + c4 * 4] = *(const float4*)&Xh[(size_t)(m0 + r) * K2 + kc + c4 * 4];
            *(float4*)&Al[r * GM_STRIDE + c4 * 4] = *(const float4*)&Xl[(size_t)(m0 + r) * K2 + kc + c4 * 4];
            *(float4*)&Bh[r * GM_STRIDE + c4 * 4] = *(const float4*)&Wh[(size_t)(n0 + r) * K2 + kc + c4 * 4];
            *(float4*)&Bl[r * GM_STRIDE + c4 * 4] = *(const float4*)&Wl[(size_t)(n0 + r) * K2 + kc + c4 * 4];
        }
        __syncthreads();

        #pragma unroll
        for (int ks = 0; ks < 4; ks++) {
            uint32_t kb = (ks * 8) * 4;
            unsigned bhf[2][4], blf[2][4];
            #pragma unroll
            for (int p = 0; p < 2; p++) {
                uint32_t ba = (brow_base + p * 16) * GM_STRIDE * 4 + kb + boff;
                LDSM_X4(bhf[p][0], bhf[p][1], bhf[p][2], bhf[p][3], sBh + ba);
                LDSM_X4(blf[p][0], blf[p][1], blf[p][2], blf[p][3], sBl + ba);
            }
            #pragma unroll
            for (int mt = 0; mt < 4; mt++) {
                uint32_t aa = (arow + mt * 16) * GM_STRIDE * 4 + kb + aoff;
                unsigned ah[4], al[4];
                LDSM_X4(ah[0], ah[1], ah[2], ah[3], sAh + aa);
                LDSM_X4(al[0], al[1], al[2], al[3], sAl + aa);
                #pragma unroll
                for (int nt = 0; nt < 4; nt++) {
                    unsigned b0 = bhf[nt >> 1][nt & 1], b1 = bhf[nt >> 1][2 + (nt & 1)];
                    unsigned c0 = blf[nt >> 1][nt & 1], c1 = blf[nt >> 1][2 + (nt & 1)];
                    mma_bf16(acc[mt][nt], ah[0], ah[1], ah[2], ah[3], b0, b1);
                    mma_bf16(acc[mt][nt], ah[0], ah[1], ah[2], ah[3], c0, c1);
                    mma_bf16(acc[mt][nt], al[0], al[1], al[2], al[3], b0, b1);
                }
            }
        }
    }

    int g = lane >> 2, t4 = lane & 3;
    #pragma unroll
    for (int mt = 0; mt < 4; mt++) {
        int row = m0 + wm * 64 + mt * 16 + g;
        #pragma unroll
        for (int nt = 0; nt < 4; nt++) {
            int col = n0 + wn * 32 + nt * 8 + 2 * t4;
            *(float2*)&C[(size_t)row * N + col]       = make_float2(acc[mt][nt][0], acc[mt][nt][1]);
            *(float2*)&C[(size_t)(row + 8) * N + col] = make_float2(acc[mt][nt][2], acc[mt][nt][3]);
        }
    }
}

// ======================= PBC expand + RoPE + pre-split ======================
__global__ __launch_bounds__(256)
void rope_expand_t(const int* __restrict__ outcell)
{
    __shared__ float sk[32][68];
    __shared__ float sv[32][68];
    int s0 = blockIdx.x * 32, h = blockIdx.y, b = blockIdx.z;
    int t = threadIdx.x;
    size_t bh = (size_t)b * NHh + h;
    const float LOG1E4 = 9.210340371976184f;

    #pragma unroll
    for (int i = 0; i < 2; i++) {
        int idx = t + i * 256;
        int r = idx >> 4, c4 = idx & 15;
        int s = s0 + r;
        int src = (s < Tt) ? s : outcell[b * Ee + (s - Tt)];
        *(float4*)&sk[r][c4 * 4] =
            ((const float4*)(g_kp + ((size_t)b * Tt + src) * Hh + h * 64))[c4];
        *(float4*)&sv[r][c4 * 4] =
            ((const float4*)(g_vp + ((size_t)b * Tt + src) * Hh + h * 64))[c4];
    }
    __syncthreads();

    #pragma unroll
    for (int i = 0; i < 4; i++) {
        int idx = t + i * 256;
        int d2 = idx >> 5, sl = idx & 31;
        int sabs = s0 + sl;
        int d0 = 2 * d2, d1 = d0 + 1;
        float invf0 = expf(-((float)(2 * (d0 & 31)) / 64.0f) * LOG1E4);
        float invf1 = expf(-((float)(2 * (d1 & 31)) / 64.0f) * LOG1E4);
        float a0 = (float)sabs * invf0, a1 = (float)sabs * invf1;
        float c0 = cosf(a0), n0 = sinf(a0), c1 = cosf(a1), n1 = sinf(a1);
        float v0 = (d0 < 32) ? sk[sl][d0] * c0 - sk[sl][d0 + 32] * n0
                             : sk[sl][d0] * c0 + sk[sl][d0 - 32] * n0;
        float v1 = (d1 < 32) ? sk[sl][d1] * c1 - sk[sl][d1 + 32] * n1
                             : sk[sl][d1] * c1 + sk[sl][d1 - 32] * n1;
        unsigned hp, lp; split2(v0, v1, hp, lp);
        g_kh[(bh * 32 + d2) * (size_t)Ss + sabs] = hp;
        g_kl[(bh * 32 + d2) * (size_t)Ss + sabs] = lp;
    }

    #pragma unroll
    for (int i = 0; i < 4; i++) {
        int idx = t + i * 256;
        int s2 = idx >> 6, d = idx & 63;
        unsigned hp, lp; split2(sv[2 * s2][d], sv[2 * s2 + 1][d], hp, lp);
        g_vh[(bh * 768 + (s0 >> 1) + s2) * 64 + d] = hp;
        g_vl[(bh * 768 + (s0 >> 1) + s2) * 64 + d] = lp;
    }

    if (s0 >= Tt) return;

    __syncthreads();
    #pragma unroll
    for (int i = 0; i < 2; i++) {
        int idx = t + i * 256;
        int r = idx >> 4, c4 = idx & 15;
        *(float4*)&sk[r][c4 * 4] =
            ((const float4*)(g_qp + ((size_t)b * Tt + s0 + r) * Hh + h * 64))[c4];
    }
    __syncthreads();
    #pragma unroll
    for (int i = 0; i < 4; i++) {
        int idx = t + i * 256;
        int q = idx >> 5, d2 = idx & 31;
        int sabs = s0 + q;
        int d0 = 2 * d2, d1 = d0 + 1;
        float invf0 = expf(-((float)(2 * (d0 & 31)) / 64.0f) * LOG1E4);
        float invf1 = expf(-((float)(2 * (d1 & 31)) / 64.0f) * LOG1E4);
        float a0 = (float)sabs * invf0, a1 = (float)sabs * invf1;
        float c0 = cosf(a0), n0 = sinf(a0), c1 = cosf(a1), n1 = sinf(a1);
        float v0 = (d0 < 32) ? sk[q][d0] * c0 - sk[q][d0 + 32] * n0
                             : sk[q][d0] * c0 + sk[q][d0 - 32] * n0;
        float v1 = (d1 < 32) ? sk[q][d1] * c1 - sk[q][d1 + 32] * n1
                             : sk[q][d1] * c1 + sk[q][d1 - 32] * n1;
        unsigned hp, lp; split2(v0, v1, hp, lp);
        g_qh[((bh * Tt) + sabs) * 32 + d2] = hp;
        g_ql[((bh * Tt) + sabs) * 32 + d2] = lp;
    }
}

// ======================= Flash attention v5: occupancy 2 ====================
// Q frags in registers, P reg-reuse (no P smem), K/V cp.async double-buffered.
#define A5_ARR 2304                    // 32*72 u32 per array
#define A5_BUF (4 * A5_ARR)            // Kh,Kl,Vh,Vl
#define A5_SMEM_BYTES (2 * A5_BUF * 4) // 73728

__global__ __launch_bounds__(256, 2)
void attn5(const float* __restrict__ bias, const float* __restrict__ lw,
           const unsigned char* __restrict__ kpm, const unsigned char* __restrict__ em)
{
    extern __shared__ unsigned su[];
    int t = threadIdx.x;
    int lane = t & 31, w = t >> 5;
    int g = lane >> 2, t4 = lane & 3;
    int qt = blockIdx.x, h = blockIdx.y, b = blockIdx.z;
    size_t bh = (size_t)b * NHh + h;
    int q0 = qt * 128;
    int qb = w * 16;

    // ---- Q fragments in registers (loop-invariant) ----
    unsigned qfh[4][4], qfl[4][4];
    {
        const unsigned* qhp = g_qh + ((bh * Tt) + q0 + qb) * 32;
        const unsigned* qlp = g_ql + ((bh * Tt) + q0 + qb) * 32;
        #pragma unroll
        for (int dc = 0; dc < 4; dc++) {
            int c0 = dc * 8 + t4;
            qfh[dc][0] = qhp[g * 32 + c0];
            qfh[dc][1] = qhp[(g + 8) * 32 + c0];
            qfh[dc][2] = qhp[g * 32 + c0 + 4];
            qfh[dc][3] = qhp[(g + 8) * 32 + c0 + 4];
            qfl[dc][0] = qlp[g * 32 + c0];
            qfl[dc][1] = qlp[(g + 8) * 32 + c0];
            qfl[dc][2] = qlp[g * 32 + c0 + 4];
            qfl[dc][3] = qlp[(g + 8) * 32 + c0 + 4];
        }
    }

    uint32_t sbase = smem_to_u32(su);
    int sr0 = t >> 4, sc0 = (t & 15) * 4;
    int sr1 = (t + 256) >> 4, sc1 = ((t + 256) & 15) * 4;

    float m0 = -INFINITY, m1 = -INFINITY, l0 = 0.f, l1 = 0.f;
    float oacc[8][4] = {};

    const float* biasr = bias + ((bh * Tt) + q0 + qb + g) * (size_t)Ss;
    const float* lwr   = lw + ((size_t)b * Tt + q0 + qb + g) * (size_t)Ss;

    // issue tile kt into buffer buf
    #define A5_ISSUE(kt_, buf_) do {                                               \
        int k0_ = (kt_) * 64;                                                      \
        uint32_t o_ = sbase + (buf_) * A5_BUF * 4;                                 \
        CP16(o_ + (sr0 * 72 + sc0) * 4,                 &g_kh[(bh * 32 + sr0) * (size_t)Ss + k0_ + sc0]); \
        CP16(o_ + (A5_ARR + sr0 * 72 + sc0) * 4,        &g_kl[(bh * 32 + sr0) * (size_t)Ss + k0_ + sc0]); \
        CP16(o_ + (2 * A5_ARR + sr0 * 72 + sc0) * 4,    &g_vh[(bh * 768 + (k0_ >> 1) + sr0) * 64 + sc0]); \
        CP16(o_ + (3 * A5_ARR + sr0 * 72 + sc0) * 4,    &g_vl[(bh * 768 + (k0_ >> 1) + sr0) * 64 + sc0]); \
        CP16(o_ + (sr1 * 72 + sc1) * 4,                 &g_kh[(bh * 32 + sr1) * (size_t)Ss + k0_ + sc1]); \
        CP16(o_ + (A5_ARR + sr1 * 72 + sc1) * 4,        &g_kl[(bh * 32 + sr1) * (size_t)Ss + k0_ + sc1]); \
        CP16(o_ + (2 * A5_ARR + sr1 * 72 + sc1) * 4,    &g_vh[(bh * 768 + (k0_ >> 1) + sr1) * 64 + sc1]); \
        CP16(o_ + (3 * A5_ARR + sr1 * 72 + sc1) * 4,    &g_vl[(bh * 768 + (k0_ >> 1) + sr1) * 64 + sc1]); \
        CP_COMMIT();                                                               \
    } while (0)

    A5_ISSUE(0, 0);

    const int NT = Ss / 64;
    for (int kt = 0; kt < NT; kt++) {
        int k0 = kt * 64;
        int buf = kt & 1;
        if (kt + 1 < NT) {
            A5_ISSUE(kt + 1, buf ^ 1);
            asm volatile("cp.async.wait_group 1;" ::: "memory");
        } else {
            asm volatile("cp.async.wait_group 0;" ::: "memory");
        }
        __syncthreads();

        unsigned* Kh = su + buf * A5_BUF;
        unsigned* Kl = Kh + A5_ARR;
        unsigned* Vh = Kl + A5_ARR;
        unsigned* Vl = Vh + A5_ARR;

        // ---- QK: 16q x 64k per warp ----
        float sc[8][4];
        #pragma unroll
        for (int ns = 0; ns < 8; ns++)
            #pragma unroll
            for (int j = 0; j < 4; j++) sc[ns][j] = 0.f;

        #pragma unroll
        for (int dc = 0; dc < 4; dc++) {
            #pragma unroll
            for (int ns = 0; ns < 8; ns++) {
                unsigned bh0 = Kh[(dc * 8 + t4) * 72 + ns * 8 + g];
                unsigned bh1 = Kh[(dc * 8 + t4 + 4) * 72 + ns * 8 + g];
                unsigned bl0 = Kl[(dc * 8 + t4) * 72 + ns * 8 + g];
                unsigned bl1 = Kl[(dc * 8 + t4 + 4) * 72 + ns * 8 + g];
                mma_bf16(sc[ns], qfh[dc][0], qfh[dc][1], qfh[dc][2], qfh[dc][3], bh0, bh1);
                mma_bf16(sc[ns], qfh[dc][0], qfh[dc][1], qfh[dc][2], qfh[dc][3], bl0, bl1);
                mma_bf16(sc[ns], qfl[dc][0], qfl[dc][1], qfl[dc][2], qfl[dc][3], bh0, bh1);
            }
        }

        // ---- bias + masks (lw NOT kept in regs; reloaded at exp time) ----
        float tm0 = -INFINITY, tm1 = -INFINITY;
        #pragma unroll
        for (int ns = 0; ns < 8; ns++) {
            int kb = k0 + ns * 8 + 2 * t4;
            float2 b0v = *(const float2*)(biasr + kb);
            float2 b1v = *(const float2*)(biasr + 8 * (size_t)Ss + kb);
            float2 l0v = *(const float2*)(lwr + kb);
            float2 l1v = *(const float2*)(lwr + 8 * (size_t)Ss + kb);
            unsigned char ma0, ma1;
            if (k0 < Tt) { ma0 = kpm[b * Tt + kb]; ma1 = kpm[b * Tt + kb + 1]; }
            else         { ma0 = em[b * Ee + kb - Tt]; ma1 = em[b * Ee + kb - Tt + 1]; }
            sc[ns][0] = (l0v.x <= 1e-5f || ma0) ? -INFINITY : sc[ns][0] + b0v.x;
            sc[ns][1] = (l0v.y <= 1e-5f || ma1) ? -INFINITY : sc[ns][1] + b0v.y;
            sc[ns][2] = (l1v.x <= 1e-5f || ma0) ? -INFINITY : sc[ns][2] + b1v.x;
            sc[ns][3] = (l1v.y <= 1e-5f || ma1) ? -INFINITY : sc[ns][3] + b1v.y;
            tm0 = fmaxf(tm0, fmaxf(sc[ns][0], sc[ns][1]));
            tm1 = fmaxf(tm1, fmaxf(sc[ns][2], sc[ns][3]));
        }
        tm0 = fmaxf(tm0, __shfl_xor_sync(0xffffffffu, tm0, 1));
        tm0 = fmaxf(tm0, __shfl_xor_sync(0xffffffffu, tm0, 2));
        tm1 = fmaxf(tm1, __shfl_xor_sync(0xffffffffu, tm1, 1));
        tm1 = fmaxf(tm1, __shfl_xor_sync(0xffffffffu, tm1, 2));

        float mn0 = fmaxf(m0, tm0);
        float mn1 = fmaxf(m1, tm1);
        float scl0 = (mn0 > -INFINITY) ? __expf(m0 - mn0) : 1.0f;
        float scl1 = (mn1 > -INFINITY) ? __expf(m1 - mn1) : 1.0f;
        float mc0 = (mn0 > -INFINITY) ? mn0 : 0.0f;
        float mc1 = (mn1 > -INFINITY) ? mn1 : 0.0f;

        // ---- exp + P fragments straight into registers (no smem) ----
        unsigned ph[8][2], pl[8][2];
        float es0 = 0.f, es1 = 0.f;
        #pragma unroll
        for (int ns = 0; ns < 8; ns++) {
            int kb = k0 + ns * 8 + 2 * t4;
            float2 l0v = *(const float2*)(lwr + kb);                 // L1-hot reload
            float2 l1v = *(const float2*)(lwr + 8 * (size_t)Ss + kb);
            float e0 = __expf(sc[ns][0] - mc0);
            float e1 = __expf(sc[ns][1] - mc0);
            float e2 = __expf(sc[ns][2] - mc1);
            float e3 = __expf(sc[ns][3] - mc1);
            es0 += e0 + e1; es1 += e2 + e3;
            split2(e0 * l0v.x, e1 * l0v.y, ph[ns][0], pl[ns][0]);
            split2(e2 * l1v.x, e3 * l1v.y, ph[ns][1], pl[ns][1]);
        }
        es0 += __shfl_xor_sync(0xffffffffu, es0, 1);
        es0 += __shfl_xor_sync(0xffffffffu, es0, 2);
        es1 += __shfl_xor_sync(0xffffffffu, es1, 1);
        es1 += __shfl_xor_sync(0xffffffffu, es1, 2);
        l0 = l0 * scl0 + es0; m0 = mn0;
        l1 = l1 * scl1 + es1; m1 = mn1;

        #pragma unroll
        for (int ns = 0; ns < 8; ns++) {
            oacc[ns][0] *= scl0; oacc[ns][1] *= scl0;
            oacc[ns][2] *= scl1; oacc[ns][3] *= scl1;
        }

        // ---- PV: A-fragments from registers, B from smem ----
        #pragma unroll
        for (int kc = 0; kc < 4; kc++) {
            unsigned ah0 = ph[2 * kc][0], ah1 = ph[2 * kc][1];
            unsigned ah2 = ph[2 * kc + 1][0], ah3 = ph[2 * kc + 1][1];
            unsigned al0 = pl[2 * kc][0], al1 = pl[2 * kc][1];
            unsigned al2 = pl[2 * kc + 1][0], al3 = pl[2 * kc + 1][1];
            #pragma unroll
            for (int ns = 0; ns < 8; ns++) {
                unsigned b0 = Vh[(kc * 8 + t4) * 72 + ns * 8 + g];
                unsigned b1 = Vh[(kc * 8 + t4 + 4) * 72 + ns * 8 + g];
                unsigned c0 = Vl[(kc * 8 + t4) * 72 + ns * 8 + g];
                unsigned c1 = Vl[(kc * 8 + t4 + 4) * 72 + ns * 8 + g];
                mma_bf16(oacc[ns], ah0, ah1, ah2, ah3, b0, b1);
                mma_bf16(oacc[ns], ah0, ah1, ah2, ah3, c0, c1);
                mma_bf16(oacc[ns], al0, al1, al2, al3, b0, b1);
            }
        }
        __syncthreads();   // all warps done reading this buffer
    }

    float i0 = 1.0f / l0, i1 = 1.0f / l1;
    int r0 = q0 + qb + g;
    #pragma unroll
    for (int ns = 0; ns < 8; ns++) {
        float2 o0 = make_float2(oacc[ns][0] * i0, oacc[ns][1] * i0);
        float2 o1 = make_float2(oacc[ns][2] * i1, oacc[ns][3] * i1);
        *(float2*)&g_attn[((size_t)b * Tt + r0) * Hh + h * 64 + ns * 8 + 2 * t4] = o0;
        *(float2*)&g_attn[((size_t)b * Tt + r0 + 8) * Hh + h * 64 + ns * 8 + 2 * t4] = o1;
    }
}

// ---- layernorm over H=1024, emits packed hi/lo for out-proj GEMM ----
__global__ void ln_kernel(const float* __restrict__ gamma, const float* __restrict__ beta)
{
    int row = blockIdx.x;
    int tid = threadIdx.x;
    float4 v = *(const float4*)&g_attn[(size_t)row * Hh + tid * 4];
    float s = v.x + v.y + v.z + v.w;
    float s2 = v.x * v.x + v.y * v.y + v.z * v.z + v.w * v.w;
    __shared__ float rs[256], rs2[256];
    rs[tid] = s; rs2[tid] = s2;
    __syncthreads();
    for (int st = 128; st > 0; st >>= 1) {
        if (tid < st) { rs[tid] += rs[tid + st]; rs2[tid] += rs2[tid + st]; }
        __syncthreads();
    }
    float mean = rs[0] * (1.0f / Hh);
    float var  = rs2[0] * (1.0f / Hh) - mean * mean;
    float r = rsqrtf(var + 1e-5f);
    float4 gm = *(const float4*)&gamma[tid * 4];
    float4 bt = *(const float4*)&beta[tid * 4];
    float n0 = (v.x - mean) * r * gm.x + bt.x;
    float n1 = (v.y - mean) * r * gm.y + bt.y;
    float n2 = (v.z - mean) * r * gm.z + bt.z;
    float n3 = (v.w - mean) * r * gm.w + bt.w;
    unsigned h0, l0v, h1, l1v;
    split2(n0, n1, h0, l0v);
    split2(n2, n3, h1, l1v);
    *(uint2*)&g_nh[(size_t)row * 512 + tid * 2] = make_uint2(h0, h1);
    *(uint2*)&g_nl[(size_t)row * 512 + tid * 2] = make_uint2(l0v, l1v);
}

extern "C" void kernel_launch(void* const* d_in, const int* in_sizes, int n_in,
                              void* d_out, int out_size)
{
    const float* x    = (const float*)d_in[0];
    const float* bias = (const float*)d_in[1];
    const float* lw   = (const float*)d_in[2];
    const unsigned char* kpm = (const unsigned char*)d_in[3];
    const int*   outcell = (const int*)d_in[4];
    const unsigned char* em  = (const unsigned char*)d_in[5];
    const float* wq   = (const float*)d_in[6];
    const float* wk   = (const float*)d_in[7];
    const float* wv   = (const float*)d_in[8];
    const float* wout = (const float*)d_in[9];
    const float* lng  = (const float*)d_in[10];
    const float* lnb  = (const float*)d_in[11];

    float *qp, *kp, *vp;
    unsigned *xh, *xl, *wqh, *wql, *wkh, *wkl, *wvh, *wvl, *woh, *wol, *nh, *nl;
    cudaGetSymbolAddress((void**)&qp,  g_qp);
    cudaGetSymbolAddress((void**)&kp,  g_kp);
    cudaGetSymbolAddress((void**)&vp,  g_vp);
    cudaGetSymbolAddress((void**)&xh,  g_xh);  cudaGetSymbolAddress((void**)&xl,  g_xl);
    cudaGetSymbolAddress((void**)&wqh, g_wqh); cudaGetSymbolAddress((void**)&wql, g_wql);
    cudaGetSymbolAddress((void**)&wkh, g_wkh); cudaGetSymbolAddress((void**)&wkl, g_wkl);
    cudaGetSymbolAddress((void**)&wvh, g_wvh); cudaGetSymbolAddress((void**)&wvl, g_wvl);
    cudaGetSymbolAddress((void**)&woh, g_woh); cudaGetSymbolAddress((void**)&wol, g_wol);
    cudaGetSymbolAddress((void**)&nh,  g_nh);  cudaGetSymbolAddress((void**)&nl,  g_nl);

    static int attr_set = 0;
    if (!attr_set) {
        cudaFuncSetAttribute(attn5, cudaFuncAttributeMaxDynamicSharedMemorySize,
                             A5_SMEM_BYTES);
        cudaFuncSetAttribute(gemm_mma, cudaFuncAttributeMaxDynamicSharedMemorySize,
                             GM_SMEM_BYTES);
        attr_set = 1;
    }

    int tot = XP + 4 * WP;
    splitk_all<<<(tot + 255) / 256, 256>>>(x, wq, wk, wv, wout,
        xh, xl, wqh, wql, wkh, wkl, wvh, wvl, woh, wol);

    gemm_mma<<<dim3(Hh / 128, (Bb * Tt) / 128, 3), 256, GM_SMEM_BYTES>>>(
        xh, xl, wqh, wql, wkh, wkl, wvh, wvl, qp, kp, vp, Hh, Hh);

    rope_expand_t<<<dim3(Ss / 32, NHh, Bb), 256>>>(outcell);

    attn5<<<dim3(Tt / 128, NHh, Bb), 256, A5_SMEM_BYTES>>>(bias, lw, kpm, em);

    ln_kernel<<<Bb * Tt, 256>>>(lng, lnb);

    gemm_mma<<<dim3(Hh / 128, (Bb * Tt) / 128, 1), 256, GM_SMEM_BYTES>>>(
        nh, nl, woh, wol, woh, wol, woh, wol,
        (float*)d_out, (float*)d_out, (float*)d_out, Hh, Hh);
}